// round 1
// baseline (speedup 1.0000x reference)
#include <cuda_runtime.h>
#include <math.h>

#define Bq   64
#define Pq   196
#define EDq  2048
#define ADq  512
#define DDq  512
#define Eq   300
#define Vq   1000
#define Tq   96
#define TD   95
#define KCAT 2860   // (E + ED) + DD = 2348 + 512
#define G4   2048   // 4*DD
#define SPL  8

// output layout (flattened fp32, in reference-return order)
#define OUT_PRED    0LL                         // 64*95*1000 = 6,080,000
#define OUT_CAPS    6080000LL                   // 64*96      = 6,144
#define OUT_DECLEN  6086144LL                   // 64
#define OUT_ALPHAS  6086208LL                   // 64*95*196  = 1,191,680
#define OUT_SORTIND 7277888LL                   // 64
#define OUT_TOTAL   7277952LL

// ---------------- scratch (static device globals; allocation-free) -------------
__device__ int   g_sortind[Bq];
__device__ int   g_declen[Bq];
__device__ int   g_caps[Bq * Tq];
__device__ float g_eos[(long long)Bq * Pq * EDq];     // sorted encoder_out, ~98MB
__device__ float g_att1[(long long)Bq * Pq * ADq];    // ~24.5MB
__device__ float g_meaneo[Bq * EDq];
__device__ float g_h[Bq * DDq];
__device__ float g_c[Bq * DDq];
__device__ float g_att2[Bq * ADq];
__device__ float g_alpha[Bq * Pq];
__device__ float g_gate[Bq * EDq];
__device__ float g_xcat[Bq * KCAT];                   // [emb_t | gate*awe | h]
__device__ float g_wcat[(long long)KCAT * G4];        // [W_ih ; W_hh], ~23.4MB
__device__ float g_biasg[G4];                         // b_ih + b_hh
__device__ float g_part[(long long)SPL * Bq * G4];    // split-K partials

__device__ __forceinline__ float sigf(float x) { return 1.0f / (1.0f + expf(-x)); }

// ---------------- sort (stable descending by length) + caps gather -------------
__global__ void k_sort(const int* __restrict__ lens, const int* __restrict__ caps,
                       float* __restrict__ out)
{
    int i = threadIdx.x;  // original index
    int li = lens[i];
    int r = 0;
    for (int j = 0; j < Bq; j++) {
        int lj = lens[j];
        if (lj > li || (lj == li && j < i)) r++;
    }
    g_sortind[r] = i;
    __syncthreads();
    // now thread i acts as rank i
    int src = g_sortind[i];
    int dl = lens[src] - 1;
    g_declen[i] = dl;
    out[OUT_DECLEN + i]  = (float)dl;
    out[OUT_SORTIND + i] = (float)src;
    for (int tt = 0; tt < Tq; tt++) {
        int v = caps[src * Tq + tt];
        g_caps[i * Tq + tt] = v;
        out[OUT_CAPS + i * Tq + tt] = (float)v;
    }
}

// ---------------- gather encoder_out rows in sorted order ----------------------
__global__ void k_gather(const float* __restrict__ eo)
{
    int bp = blockIdx.x;                 // b*196 + p
    int b = bp / Pq, p = bp % Pq;
    int src = g_sortind[b];
    const float* s = eo + ((long long)(src * Pq + p)) * EDq;
    float* d = g_eos + (long long)bp * EDq;
    for (int i = threadIdx.x; i < EDq; i += blockDim.x) d[i] = s[i];
}

// ---------------- concat [W_ih ; W_hh] and bias sum -----------------------------
__global__ void k_wcat(const float* __restrict__ Wih, const float* __restrict__ Whh,
                       const float* __restrict__ bih, const float* __restrict__ bhh)
{
    long long idx = (long long)blockIdx.x * blockDim.x + threadIdx.x;
    if (idx < (long long)KCAT * G4) {
        int row = (int)(idx / G4), col = (int)(idx % G4);
        g_wcat[idx] = (row < 2348) ? Wih[idx] : Whh[(long long)(row - 2348) * G4 + col];
    }
    if (idx < G4) g_biasg[idx] = bih[idx] + bhh[idx];
}

// ---------------- mean over P -----------------------------------------------------
__global__ void k_mean()
{
    int b = blockIdx.x;
    for (int e = threadIdx.x; e < EDq; e += blockDim.x) {
        float s = 0.0f;
        const float* base = g_eos + (long long)b * Pq * EDq + e;
        for (int p = 0; p < Pq; p++) s += base[(long long)p * EDq];
        g_meaneo[b * EDq + e] = s * (1.0f / (float)Pq);
    }
}

// ---------------- generic tiled fp32 GEMM: C = A[M,K] @ B[K,N] (+epilogue) -------
// grid: (ceil(N/64), Mtiles, S). mode: 0=+bias, 1=sigmoid(+bias), 2=raw partial,
// 3=(+bias)*rowmask (preds, row m == batch b).
__global__ void __launch_bounds__(256)
k_gemm(const float* __restrict__ A, int lda,
       const float* __restrict__ B, int ldb,
       float* __restrict__ C, int ldcRow, long long cSplitStride,
       int N, int K, int S,
       const float* __restrict__ bias, int mode, int t)
{
    int nt = blockIdx.x, mt = blockIdx.y, z = blockIdx.z;
    int k0 = (int)((long long)K * z / S);
    int k1 = (int)((long long)K * (z + 1) / S);
    C += (long long)z * cSplitStride;
    int row0 = mt * 64, col0 = nt * 64;

    __shared__ float As[16][65];
    __shared__ float Bs[16][65];
    int tid = threadIdx.x, tx = tid & 15, ty = tid >> 4;
    float acc[4][4] = {};

    for (int kb = k0; kb < k1; kb += 16) {
#pragma unroll
        for (int l = 0; l < 4; l++) {
            int idx = tid + l * 256;
            int m = idx >> 4, kk = idx & 15;
            int kg = kb + kk;
            As[kk][m] = (kg < k1) ? A[(long long)(row0 + m) * lda + kg] : 0.0f;
        }
#pragma unroll
        for (int l = 0; l < 4; l++) {
            int idx = tid + l * 256;
            int kk = idx >> 6, n = idx & 63;
            int kg = kb + kk, ng = col0 + n;
            Bs[kk][n] = (kg < k1 && ng < N) ? B[(long long)kg * ldb + ng] : 0.0f;
        }
        __syncthreads();
#pragma unroll
        for (int kk = 0; kk < 16; kk++) {
#pragma unroll
            for (int i = 0; i < 4; i++) {
                float av = As[kk][ty * 4 + i];
#pragma unroll
                for (int j = 0; j < 4; j++) acc[i][j] += av * Bs[kk][tx * 4 + j];
            }
        }
        __syncthreads();
    }

#pragma unroll
    for (int i = 0; i < 4; i++) {
        int m = row0 + ty * 4 + i;
#pragma unroll
        for (int j = 0; j < 4; j++) {
            int n = col0 + tx * 4 + j;
            if (n < N) {
                float v = acc[i][j];
                if (mode == 0 || mode == 1 || mode == 3) v += bias[n];
                if (mode == 1) v = sigf(v);
                if (mode == 3) v *= (g_declen[m] > t) ? 1.0f : 0.0f;
                C[(long long)m * ldcRow + n] = v;
            }
        }
    }
}

// ---------------- attention: e, softmax, alpha; also stage xcat emb & h ----------
__global__ void k_attention(const float* __restrict__ wfull, const float* __restrict__ bfull,
                            const float* __restrict__ emb, float* __restrict__ out, int t)
{
    int b = blockIdx.x, tid = threadIdx.x;
    __shared__ float sh_att2[ADq];
    __shared__ float sh_w[ADq];
    __shared__ float sh_e[224];
    __shared__ float red[8];

    for (int i = tid; i < ADq; i += 256) {
        sh_att2[i] = g_att2[b * ADq + i];
        sh_w[i] = wfull[i];
    }
    // stage xcat: h tail + embedding head (h is pre-update for this step)
    for (int i = tid; i < DDq; i += 256)
        g_xcat[b * KCAT + 2348 + i] = g_h[b * DDq + i];
    int tok = g_caps[b * Tq + t];
    for (int i = tid; i < Eq; i += 256)
        g_xcat[b * KCAT + i] = emb[(long long)tok * Eq + i];
    __syncthreads();

    int wrp = tid >> 5, lane = tid & 31;
    for (int p = wrp; p < Pq; p += 8) {
        const float* a1 = g_att1 + ((long long)(b * Pq + p)) * ADq;
        float s = 0.0f;
        for (int a = lane; a < ADq; a += 32) {
            float v = a1[a] + sh_att2[a];
            v = v > 0.0f ? v : 0.0f;
            s += v * sh_w[a];
        }
        for (int o = 16; o > 0; o >>= 1) s += __shfl_down_sync(0xffffffffu, s, o);
        if (lane == 0) sh_e[p] = s + bfull[0];
    }
    __syncthreads();

    // softmax over P=196
    float mval = -1e30f;
    if (tid < Pq) mval = sh_e[tid];
    for (int o = 16; o > 0; o >>= 1) mval = fmaxf(mval, __shfl_down_sync(0xffffffffu, mval, o));
    if (lane == 0) red[wrp] = mval;
    __syncthreads();
    if (tid == 0) {
        float m2 = red[0];
        for (int i = 1; i < 8; i++) m2 = fmaxf(m2, red[i]);
        red[0] = m2;
    }
    __syncthreads();
    float mx = red[0];
    __syncthreads();

    float ex = 0.0f;
    if (tid < Pq) {
        ex = expf(sh_e[tid] - mx);
        sh_e[tid] = ex;
    }
    float se = ex;
    for (int o = 16; o > 0; o >>= 1) se += __shfl_down_sync(0xffffffffu, se, o);
    if (lane == 0) red[wrp] = se;
    __syncthreads();
    if (tid == 0) {
        float s2 = 0.0f;
        for (int i = 0; i < 8; i++) s2 += red[i];
        red[0] = s2;
    }
    __syncthreads();
    float ssum = red[0];

    float mk = (g_declen[b] > t) ? 1.0f : 0.0f;
    if (tid < Pq) {
        float al = sh_e[tid] / ssum;
        g_alpha[b * Pq + tid] = al;
        out[OUT_ALPHAS + (long long)b * TD * Pq + (long long)t * Pq + tid] = al * mk;
    }
}

// ---------------- awe = eo^T alpha, fused with gate multiply into xcat ------------
__global__ void k_awe()
{
    int b = blockIdx.y, ch = blockIdx.x;
    int e = ch * 128 + threadIdx.x;
    __shared__ float sa[Pq];
    for (int p = threadIdx.x; p < Pq; p += 128) sa[p] = g_alpha[b * Pq + p];
    __syncthreads();
    float s = 0.0f;
    const float* base = g_eos + (long long)b * Pq * EDq + e;
    for (int p = 0; p < Pq; p++) s += sa[p] * base[(long long)p * EDq];
    g_xcat[b * KCAT + Eq + e] = g_gate[b * EDq + e] * s;
}

// ---------------- LSTM cell: reduce split-K partials, update h,c with mask -------
__global__ void k_lstm(int t)
{
    int b = blockIdx.x, d = threadIdx.x;
    float i_ = 0.0f, f_ = 0.0f, gg = 0.0f, o_ = 0.0f;
    for (int s = 0; s < SPL; s++) {
        const float* p = g_part + ((long long)s * Bq + b) * G4;
        i_ += p[d];
        f_ += p[512 + d];
        gg += p[1024 + d];
        o_ += p[1536 + d];
    }
    i_ += g_biasg[d];
    f_ += g_biasg[512 + d];
    gg += g_biasg[1024 + d];
    o_ += g_biasg[1536 + d];
    float co = g_c[b * DDq + d], ho = g_h[b * DDq + d];
    float cn = sigf(f_) * co + sigf(i_) * tanhf(gg);
    float hn = sigf(o_) * tanhf(cn);
    bool mk = (g_declen[b] > t);
    g_h[b * DDq + d] = mk ? hn : ho;
    g_c[b * DDq + d] = mk ? cn : co;
}

// =================================================================================
extern "C" void kernel_launch(void* const* d_in, const int* in_sizes, int n_in,
                              void* d_out, int out_size)
{
    const float* eo    = (const float*)d_in[0];
    const int*   caps  = (const int*)  d_in[1];
    const int*   lens  = (const int*)  d_in[2];
    const float* emb   = (const float*)d_in[3];
    const float* Wea   = (const float*)d_in[4];
    const float* bea   = (const float*)d_in[5];
    const float* Wda   = (const float*)d_in[6];
    const float* bda   = (const float*)d_in[7];
    const float* wfull = (const float*)d_in[8];
    const float* bfull = (const float*)d_in[9];
    const float* Wih0  = (const float*)d_in[10];
    const float* bih0  = (const float*)d_in[11];
    const float* Wic0  = (const float*)d_in[12];
    const float* bic0  = (const float*)d_in[13];
    const float* Wfb   = (const float*)d_in[14];
    const float* bfb   = (const float*)d_in[15];
    const float* WIH   = (const float*)d_in[16];
    const float* bIH   = (const float*)d_in[17];
    const float* WHH   = (const float*)d_in[18];
    const float* bHH   = (const float*)d_in[19];
    const float* Wfc   = (const float*)d_in[20];
    const float* bfc   = (const float*)d_in[21];
    float* out = (float*)d_out;

    float *p_eos, *p_att1, *p_meaneo, *p_h, *p_c, *p_att2, *p_gate, *p_xcat, *p_wcat, *p_part;
    cudaGetSymbolAddress((void**)&p_eos, g_eos);
    cudaGetSymbolAddress((void**)&p_att1, g_att1);
    cudaGetSymbolAddress((void**)&p_meaneo, g_meaneo);
    cudaGetSymbolAddress((void**)&p_h, g_h);
    cudaGetSymbolAddress((void**)&p_c, g_c);
    cudaGetSymbolAddress((void**)&p_att2, g_att2);
    cudaGetSymbolAddress((void**)&p_gate, g_gate);
    cudaGetSymbolAddress((void**)&p_xcat, g_xcat);
    cudaGetSymbolAddress((void**)&p_wcat, g_wcat);
    cudaGetSymbolAddress((void**)&p_part, g_part);

    // ---- setup ----
    k_sort<<<1, Bq>>>(lens, caps, out);
    k_wcat<<<(int)(((long long)KCAT * G4 + 1023) / 1024), 1024>>>(WIH, WHH, bIH, bHH);
    k_gather<<<Bq * Pq, 256>>>(eo);
    k_mean<<<Bq, 256>>>();
    // h0 = mean_eo @ W_init_h + b ; c0 likewise (M=64, K=2048, N=512)
    k_gemm<<<dim3(8, 1, 1), 256>>>(p_meaneo, EDq, Wih0, DDq, p_h, DDq, 0,
                                   DDq, EDq, 1, bih0, 0, 0);
    k_gemm<<<dim3(8, 1, 1), 256>>>(p_meaneo, EDq, Wic0, DDq, p_c, DDq, 0,
                                   DDq, EDq, 1, bic0, 0, 0);
    // att1 = eo_s @ W_enc_att + b  (M=12544, K=2048, N=512)
    k_gemm<<<dim3(8, 196, 1), 256>>>(p_eos, EDq, Wea, ADq, p_att1, ADq, 0,
                                     ADq, EDq, 1, bea, 0, 0);

    // ---- recurrence ----
    for (int t = 0; t < TD; t++) {
        // att2 = h @ W_dec_att + b   (M=64, K=512, N=512)
        k_gemm<<<dim3(8, 1, 1), 256>>>(p_h, DDq, Wda, ADq, p_att2, ADq, 0,
                                       ADq, DDq, 1, bda, 0, 0);
        // e, softmax, alpha; stage xcat emb/h
        k_attention<<<Bq, 256>>>(wfull, bfull, emb, out, t);
        // gate = sigmoid(h @ W_fbeta + b)  (M=64, K=512, N=2048)
        k_gemm<<<dim3(32, 1, 1), 256>>>(p_h, DDq, Wfb, EDq, p_gate, EDq, 0,
                                        EDq, DDq, 1, bfb, 1, 0);
        // awe + gate multiply -> xcat middle
        k_awe<<<dim3(16, Bq), 128>>>();
        // gates partials = xcat @ Wcat  (M=64, K=2860, N=2048, split-K=8)
        k_gemm<<<dim3(32, 1, SPL), 256>>>(p_xcat, KCAT, p_wcat, G4, p_part, G4,
                                          (long long)Bq * G4, G4, KCAT, SPL,
                                          (const float*)0, 2, 0);
        // LSTM cell + mask
        k_lstm<<<Bq, DDq>>>(t);
        // preds = (h2 @ W_fc + b_fc) * mask  (M=64, K=512, N=1000), strided into out
        k_gemm<<<dim3(16, 1, 1), 256>>>(p_h, DDq, Wfc, Vq,
                                        out + OUT_PRED + (long long)t * Vq,
                                        TD * Vq, 0, Vq, DDq, 1, bfc, 3, t);
    }
}

// round 2
// speedup vs baseline: 1.0654x; 1.0654x over previous
#include <cuda_runtime.h>
#include <math.h>

#define Bq   64
#define Pq   196
#define EDq  2048
#define ADq  512
#define DDq  512
#define Eq   300
#define Vq   1000
#define Tq   96
#define TD   95
#define KCAT 2860   // (E + ED) + DD = 2348 + 512
#define G4   2048   // 4*DD
#define HP   2560   // ADq + EDq (fused att2|gate width)
#define SPL  8

// output layout (flattened fp32, reference-return order)
#define OUT_PRED    0LL
#define OUT_CAPS    6080000LL
#define OUT_DECLEN  6086144LL
#define OUT_ALPHAS  6086208LL
#define OUT_SORTIND 7277888LL

// ---------------- scratch ----------------
__device__ int   g_sortind[Bq];
__device__ int   g_declen[Bq];
__device__ int   g_caps[Bq * Tq];
__device__ float g_eos[(long long)Bq * Pq * EDq];     // ~98MB sorted encoder_out
__device__ float g_att1[(long long)Bq * Pq * ADq];    // ~24.5MB
__device__ float g_meaneo[Bq * EDq];
__device__ float g_h[Bq * DDq];
__device__ float g_c[Bq * DDq];
__device__ float g_hproj[Bq * HP];                    // [att2 | sigmoid-gate]
__device__ float g_alpha[Bq * Pq];
__device__ float g_xcat[Bq * KCAT];                   // [emb_t | gate*awe | h]
__device__ float g_wcat[(long long)KCAT * G4];        // [W_ih ; W_hh]
__device__ float g_whcat[(long long)DDq * HP];        // [W_dec_att | W_fbeta]
__device__ float g_biasg[G4];                         // b_ih + b_hh
__device__ float g_part[(long long)SPL * Bq * HP];    // split-K partials (max width HP)

__device__ __forceinline__ float sigf(float x) { return 1.0f / (1.0f + expf(-x)); }

// ---------------- sort (stable descending) + caps gather ----------------
__global__ void k_sort(const int* __restrict__ lens, const int* __restrict__ caps,
                       float* __restrict__ out)
{
    int i = threadIdx.x;
    int li = lens[i];
    int r = 0;
    for (int j = 0; j < Bq; j++) {
        int lj = lens[j];
        if (lj > li || (lj == li && j < i)) r++;
    }
    g_sortind[r] = i;
    __syncthreads();
    int src = g_sortind[i];
    int dl = lens[src] - 1;
    g_declen[i] = dl;
    out[OUT_DECLEN + i]  = (float)dl;
    out[OUT_SORTIND + i] = (float)src;
    for (int tt = 0; tt < Tq; tt++) {
        int v = caps[src * Tq + tt];
        g_caps[i * Tq + tt] = v;
        out[OUT_CAPS + i * Tq + tt] = (float)v;
    }
}

// ---------------- gather encoder_out in sorted order ----------------
__global__ void k_gather(const float* __restrict__ eo)
{
    int bp = blockIdx.x;
    int b = bp / Pq, p = bp % Pq;
    int src = g_sortind[b];
    const float4* s = (const float4*)(eo + ((long long)(src * Pq + p)) * EDq);
    float4* d = (float4*)(g_eos + (long long)bp * EDq);
    for (int i = threadIdx.x; i < EDq / 4; i += blockDim.x) d[i] = s[i];
}

// ---------------- build concat weights + bias ----------------
__global__ void k_wcat(const float* __restrict__ Wih, const float* __restrict__ Whh,
                       const float* __restrict__ bih, const float* __restrict__ bhh,
                       const float* __restrict__ Wda, const float* __restrict__ Wfb)
{
    long long idx = (long long)blockIdx.x * blockDim.x + threadIdx.x;
    long long n1 = (long long)KCAT * G4;
    if (idx < n1) {
        int row = (int)(idx / G4), col = (int)(idx % G4);
        g_wcat[idx] = (row < 2348) ? Wih[idx] : Whh[(long long)(row - 2348) * G4 + col];
    }
    long long idx2 = idx - n1;
    if (idx2 >= 0 && idx2 < (long long)DDq * HP) {
        int row = (int)(idx2 / HP), col = (int)(idx2 % HP);
        g_whcat[idx2] = (col < ADq) ? Wda[(long long)row * ADq + col]
                                    : Wfb[(long long)row * EDq + (col - ADq)];
    }
    if (idx < G4) g_biasg[idx] = bih[idx] + bhh[idx];
}

// ---------------- mean over P ----------------
__global__ void k_mean()
{
    int b = blockIdx.y;
    int e = blockIdx.x * 256 + threadIdx.x;
    float s = 0.0f;
    const float* base = g_eos + (long long)b * Pq * EDq + e;
    for (int p = 0; p < Pq; p++) s += base[(long long)p * EDq];
    g_meaneo[b * EDq + e] = s * (1.0f / (float)Pq);
}

// ---------------- GEMM: C = A[64(xMtiles),K] @ B[K,N], 64x128 tile, 8x8 micro ----
// grid (ceil(N/128), Mtiles, S). mode 2 = raw split-K partial (C=g_part layout),
// mode 0 = +bias direct store.
__global__ void __launch_bounds__(128)
k_gemm2(const float* __restrict__ A, int lda,
        const float* __restrict__ B, int ldb,
        float* __restrict__ C, int ldcRow, long long cSplitStride,
        int N, int K, int S,
        const float* __restrict__ bias, int mode)
{
    int nt = blockIdx.x, mt = blockIdx.y, z = blockIdx.z;
    int kchunk = ((K + 16 * S - 1) / (16 * S)) * 16;
    int k0 = z * kchunk;
    int k1 = min(K, k0 + kchunk);
    C += (long long)z * cSplitStride;
    int col0 = nt * 128;
    int row0 = mt * 64;

    __shared__ float As[16][64];
    __shared__ float Bs[16][128];
    int tid = threadIdx.x;
    int tx = tid & 15, ty = tid >> 4;
    float acc[8][8] = {};

    for (int kb = k0; kb < k1; kb += 16) {
        // stage A: 64 rows x 16 k
#pragma unroll
        for (int l = 0; l < 2; l++) {
            int idx = tid + l * 128;
            int m = idx >> 2;
            int kq = (idx & 3) * 4;
            int kg = kb + kq;
            float4 v = make_float4(0.f, 0.f, 0.f, 0.f);
            if (kg + 3 < k1) {
                v = *(const float4*)&A[(long long)(row0 + m) * lda + kg];
            } else {
                float tmp[4] = {0.f, 0.f, 0.f, 0.f};
                for (int j = 0; j < 4; j++) if (kg + j < k1) tmp[j] = A[(long long)(row0 + m) * lda + kg + j];
                v = make_float4(tmp[0], tmp[1], tmp[2], tmp[3]);
            }
            As[kq + 0][m] = v.x; As[kq + 1][m] = v.y; As[kq + 2][m] = v.z; As[kq + 3][m] = v.w;
        }
        // stage B: 16 k x 128 n
#pragma unroll
        for (int l = 0; l < 4; l++) {
            int idx = tid + l * 128;
            int kk = idx >> 5;
            int n4 = (idx & 31) * 4;
            int kg = kb + kk, ng = col0 + n4;
            float4 v = make_float4(0.f, 0.f, 0.f, 0.f);
            if (kg < k1) {
                if (ng + 3 < N) {
                    v = *(const float4*)&B[(long long)kg * ldb + ng];
                } else {
                    float tmp[4] = {0.f, 0.f, 0.f, 0.f};
                    for (int j = 0; j < 4; j++) if (ng + j < N) tmp[j] = B[(long long)kg * ldb + ng + j];
                    v = make_float4(tmp[0], tmp[1], tmp[2], tmp[3]);
                }
            }
            *(float4*)&Bs[kk][n4] = v;
        }
        __syncthreads();
#pragma unroll
        for (int kk = 0; kk < 16; kk++) {
            float a[8], bb[8];
            *(float4*)&a[0] = *(const float4*)&As[kk][ty * 8];
            *(float4*)&a[4] = *(const float4*)&As[kk][ty * 8 + 4];
            *(float4*)&bb[0] = *(const float4*)&Bs[kk][tx * 8];
            *(float4*)&bb[4] = *(const float4*)&Bs[kk][tx * 8 + 4];
#pragma unroll
            for (int i = 0; i < 8; i++)
#pragma unroll
                for (int j = 0; j < 8; j++) acc[i][j] += a[i] * bb[j];
        }
        __syncthreads();
    }

#pragma unroll
    for (int i = 0; i < 8; i++) {
        int m = row0 + ty * 8 + i;
#pragma unroll
        for (int j = 0; j < 8; j++) {
            int n = col0 + tx * 8 + j;
            if (n < N) {
                float v = acc[i][j];
                if (mode == 0) v += bias[n];
                C[(long long)m * ldcRow + n] = v;
            }
        }
    }
}

// ---------------- split-K reduce + epilogue ----------------
// mode 0: +bias -> dst ; mode 1: hproj (n<ADq: +bias ; else sigmoid(+bias2)) ;
// mode 3: (+bias) * rowmask(t) (preds)
__global__ void k_reduce(float* __restrict__ dst, int lddst,
                         const float* __restrict__ bias, const float* __restrict__ bias2,
                         int N, int S, int mode, int t)
{
    int idx = blockIdx.x * 256 + threadIdx.x;
    if (idx >= Bq * N) return;
    int m = idx / N, n = idx % N;
    float v = 0.0f;
    for (int s = 0; s < S; s++) v += g_part[(long long)s * Bq * N + idx];
    if (mode == 0) v += bias[n];
    else if (mode == 1) {
        if (n < ADq) v += bias[n];
        else v = sigf(v + bias2[n - ADq]);
    } else if (mode == 3) {
        v = (v + bias[n]) * ((g_declen[m] > t) ? 1.0f : 0.0f);
    }
    dst[(long long)m * lddst + n] = v;
}

// ---------------- attention: e, softmax, alpha; stage xcat emb & h ----------------
__global__ void k_attention(const float* __restrict__ wfull, const float* __restrict__ bfull,
                            const float* __restrict__ emb, float* __restrict__ out, int t)
{
    int b = blockIdx.x, tid = threadIdx.x;
    __shared__ float sh_att2[ADq];
    __shared__ float sh_w[ADq];
    __shared__ float sh_e[224];
    __shared__ float red[8];

    for (int i = tid; i < ADq; i += 256) {
        sh_att2[i] = g_hproj[b * HP + i];
        sh_w[i] = wfull[i];
    }
    for (int i = tid; i < DDq; i += 256)
        g_xcat[b * KCAT + 2348 + i] = g_h[b * DDq + i];
    int tok = g_caps[b * Tq + t];
    for (int i = tid; i < Eq; i += 256)
        g_xcat[b * KCAT + i] = emb[(long long)tok * Eq + i];
    __syncthreads();

    int wrp = tid >> 5, lane = tid & 31;
    for (int p = wrp; p < Pq; p += 8) {
        const float* a1 = g_att1 + ((long long)(b * Pq + p)) * ADq;
        float s = 0.0f;
        for (int a = lane; a < ADq; a += 32) {
            float v = a1[a] + sh_att2[a];
            v = v > 0.0f ? v : 0.0f;
            s += v * sh_w[a];
        }
        for (int o = 16; o > 0; o >>= 1) s += __shfl_down_sync(0xffffffffu, s, o);
        if (lane == 0) sh_e[p] = s + bfull[0];
    }
    __syncthreads();

    float mval = -1e30f;
    if (tid < Pq) mval = sh_e[tid];
    for (int o = 16; o > 0; o >>= 1) mval = fmaxf(mval, __shfl_down_sync(0xffffffffu, mval, o));
    if (lane == 0) red[wrp] = mval;
    __syncthreads();
    if (tid == 0) {
        float m2 = red[0];
        for (int i = 1; i < 8; i++) m2 = fmaxf(m2, red[i]);
        red[0] = m2;
    }
    __syncthreads();
    float mx = red[0];
    __syncthreads();

    float ex = 0.0f;
    if (tid < Pq) { ex = expf(sh_e[tid] - mx); sh_e[tid] = ex; }
    float se = ex;
    for (int o = 16; o > 0; o >>= 1) se += __shfl_down_sync(0xffffffffu, se, o);
    if (lane == 0) red[wrp] = se;
    __syncthreads();
    if (tid == 0) {
        float s2 = 0.0f;
        for (int i = 0; i < 8; i++) s2 += red[i];
        red[0] = s2;
    }
    __syncthreads();
    float ssum = red[0];

    float mk = (g_declen[b] > t) ? 1.0f : 0.0f;
    if (tid < Pq) {
        float al = sh_e[tid] / ssum;
        g_alpha[b * Pq + tid] = al;
        out[OUT_ALPHAS + (long long)b * TD * Pq + (long long)t * Pq + tid] = al * mk;
    }
}

// ---------------- awe = eo^T alpha, fused gate multiply into xcat ----------------
__global__ void k_awe()
{
    int b = blockIdx.y, ch = blockIdx.x;
    int e = ch * 1024 + threadIdx.x * 4;
    __shared__ float sa[Pq];
    for (int p = threadIdx.x; p < Pq; p += 256) sa[p] = g_alpha[b * Pq + p];
    __syncthreads();
    float4 s = make_float4(0.f, 0.f, 0.f, 0.f);
    const float* base = g_eos + (long long)b * Pq * EDq + e;
    for (int p = 0; p < Pq; p++) {
        float4 v = *(const float4*)(base + (long long)p * EDq);
        float a = sa[p];
        s.x += a * v.x; s.y += a * v.y; s.z += a * v.z; s.w += a * v.w;
    }
    float4 g = *(const float4*)&g_hproj[b * HP + ADq + e];
    float4 r = make_float4(g.x * s.x, g.y * s.y, g.z * s.z, g.w * s.w);
    *(float4*)&g_xcat[b * KCAT + Eq + e] = r;
}

// ---------------- LSTM cell: reduce split-K partials, update h,c ----------------
__global__ void k_lstm(int t)
{
    int b = blockIdx.x, d = threadIdx.x;
    float i_ = 0.0f, f_ = 0.0f, gg = 0.0f, o_ = 0.0f;
    for (int s = 0; s < SPL; s++) {
        const float* p = g_part + ((long long)s * Bq + b) * G4;
        i_ += p[d]; f_ += p[512 + d]; gg += p[1024 + d]; o_ += p[1536 + d];
    }
    i_ += g_biasg[d];
    f_ += g_biasg[512 + d];
    gg += g_biasg[1024 + d];
    o_ += g_biasg[1536 + d];
    float co = g_c[b * DDq + d], ho = g_h[b * DDq + d];
    float cn = sigf(f_) * co + sigf(i_) * tanhf(gg);
    float hn = sigf(o_) * tanhf(cn);
    bool mk = (g_declen[b] > t);
    g_h[b * DDq + d] = mk ? hn : ho;
    g_c[b * DDq + d] = mk ? cn : co;
}

// =================================================================================
extern "C" void kernel_launch(void* const* d_in, const int* in_sizes, int n_in,
                              void* d_out, int out_size)
{
    const float* eo    = (const float*)d_in[0];
    const int*   caps  = (const int*)  d_in[1];
    const int*   lens  = (const int*)  d_in[2];
    const float* emb   = (const float*)d_in[3];
    const float* Wea   = (const float*)d_in[4];
    const float* bea   = (const float*)d_in[5];
    const float* Wda   = (const float*)d_in[6];
    const float* bda   = (const float*)d_in[7];
    const float* wfull = (const float*)d_in[8];
    const float* bfull = (const float*)d_in[9];
    const float* Wih0  = (const float*)d_in[10];
    const float* bih0  = (const float*)d_in[11];
    const float* Wic0  = (const float*)d_in[12];
    const float* bic0  = (const float*)d_in[13];
    const float* Wfb   = (const float*)d_in[14];
    const float* bfb   = (const float*)d_in[15];
    const float* WIH   = (const float*)d_in[16];
    const float* bIH   = (const float*)d_in[17];
    const float* WHH   = (const float*)d_in[18];
    const float* bHH   = (const float*)d_in[19];
    const float* Wfc   = (const float*)d_in[20];
    const float* bfc   = (const float*)d_in[21];
    float* out = (float*)d_out;

    float *p_eos, *p_att1, *p_meaneo, *p_h, *p_c, *p_hproj, *p_xcat, *p_wcat, *p_whcat, *p_part;
    cudaGetSymbolAddress((void**)&p_eos, g_eos);
    cudaGetSymbolAddress((void**)&p_att1, g_att1);
    cudaGetSymbolAddress((void**)&p_meaneo, g_meaneo);
    cudaGetSymbolAddress((void**)&p_h, g_h);
    cudaGetSymbolAddress((void**)&p_c, g_c);
    cudaGetSymbolAddress((void**)&p_hproj, g_hproj);
    cudaGetSymbolAddress((void**)&p_xcat, g_xcat);
    cudaGetSymbolAddress((void**)&p_wcat, g_wcat);
    cudaGetSymbolAddress((void**)&p_whcat, g_whcat);
    cudaGetSymbolAddress((void**)&p_part, g_part);

    // ---- setup ----
    k_sort<<<1, Bq>>>(lens, caps, out);
    {
        long long tot = (long long)KCAT * G4 + (long long)DDq * HP;
        k_wcat<<<(int)((tot + 1023) / 1024), 1024>>>(WIH, WHH, bIH, bHH, Wda, Wfb);
    }
    k_gather<<<Bq * Pq, 256>>>(eo);
    k_mean<<<dim3(8, Bq), 256>>>();
    // h0 = mean_eo @ W_init_h + b (M=64, K=2048, N=512), split-K 8
    k_gemm2<<<dim3(4, 1, 8), 128>>>(p_meaneo, EDq, Wih0, DDq, p_part, DDq,
                                    (long long)Bq * DDq, DDq, EDq, 8, (const float*)0, 2);
    k_reduce<<<(Bq * DDq + 255) / 256, 256>>>(p_h, DDq, bih0, (const float*)0, DDq, 8, 0, 0);
    k_gemm2<<<dim3(4, 1, 8), 128>>>(p_meaneo, EDq, Wic0, DDq, p_part, DDq,
                                    (long long)Bq * DDq, DDq, EDq, 8, (const float*)0, 2);
    k_reduce<<<(Bq * DDq + 255) / 256, 256>>>(p_c, DDq, bic0, (const float*)0, DDq, 8, 0, 0);
    // att1 = eo_s @ W_enc_att + b  (M=12544, K=2048, N=512)
    k_gemm2<<<dim3(4, 196, 1), 128>>>(p_eos, EDq, Wea, ADq, p_att1, ADq, 0,
                                      ADq, EDq, 1, bea, 0);

    // ---- recurrence ----
    for (int t = 0; t < TD; t++) {
        // hproj = h @ [W_dec_att | W_fbeta]  (M=64, K=512, N=2560), split-K 8
        k_gemm2<<<dim3(20, 1, 8), 128>>>(p_h, DDq, p_whcat, HP, p_part, HP,
                                         (long long)Bq * HP, HP, DDq, 8, (const float*)0, 2);
        k_reduce<<<(Bq * HP + 255) / 256, 256>>>(p_hproj, HP, bda, bfb, HP, 8, 1, t);
        // e, softmax, alpha; stage xcat emb/h
        k_attention<<<Bq, 256>>>(wfull, bfull, emb, out, t);
        // awe + gate multiply -> xcat middle
        k_awe<<<dim3(2, Bq), 256>>>();
        // gates = xcat @ Wcat  (M=64, K=2860, N=2048), split-K 8
        k_gemm2<<<dim3(16, 1, 8), 128>>>(p_xcat, KCAT, p_wcat, G4, p_part, G4,
                                         (long long)Bq * G4, G4, KCAT, 8, (const float*)0, 2);
        // LSTM cell + mask
        k_lstm<<<Bq, DDq>>>(t);
        // preds = (h2 @ W_fc + b_fc) * mask  (M=64, K=512, N=1000), split-K 8
        k_gemm2<<<dim3(8, 1, 8), 128>>>(p_h, DDq, Wfc, Vq, p_part, Vq,
                                        (long long)Bq * Vq, Vq, DDq, 8, (const float*)0, 2);
        k_reduce<<<(Bq * Vq + 255) / 256, 256>>>(out + OUT_PRED + (long long)t * Vq,
                                                 TD * Vq, bfc, (const float*)0, Vq, 8, 3, t);
    }
}

// round 3
// speedup vs baseline: 2.3895x; 2.2429x over previous
#include <cuda_runtime.h>
#include <math.h>

#define Bq   64
#define Pq   196
#define EDq  2048
#define ADq  512
#define DDq  512
#define Eq   300
#define Vq   1000
#define Tq   96
#define TD   95
#define KCAT 2860   // (E + ED) + DD = 2348 + 512
#define G4   2048   // 4*DD
#define HP   2560   // ADq + EDq (fused att2|gate width)
#define NBLK 148
#define SPL  8

// output layout (flattened fp32, reference-return order)
#define OUT_PRED    0LL
#define OUT_CAPS    6080000LL
#define OUT_DECLEN  6086144LL
#define OUT_ALPHAS  6086208LL
#define OUT_SORTIND 7277888LL

// ---------------- scratch ----------------
__device__ int   g_sortind[Bq];
__device__ int   g_declen[Bq];
__device__ int   g_caps[Bq * Tq];
__device__ float g_eos[(long long)Bq * Pq * EDq];     // sorted encoder_out ~98MB
__device__ float g_att1[(long long)Bq * Pq * ADq];    // ~24.5MB
__device__ float g_meaneo[Bq * EDq];
__device__ float g_h[Bq * DDq];
__device__ float g_c[Bq * DDq];
__device__ float g_alpha[Bq * Pq];
__device__ float g_xcat[Bq * KCAT];                   // [emb_t | gate*awe | h]
__device__ float g_wcat[(long long)KCAT * G4];        // [W_ih ; W_hh]
__device__ float g_whcat[(long long)DDq * HP];        // [W_dec_att | W_fbeta]
__device__ float g_biasg[G4];                         // b_ih + b_hh
__device__ float g_part[(long long)SPL * Bq * HP];    // setup split-K scratch
__device__ float g_partH[4LL * Bq * HP];              // hproj slices
__device__ float g_partP[8LL * Bq * Vq];              // preds slices
__device__ float g_partG[9LL * Bq * G4];              // gates slices
__device__ unsigned g_barcnt;                         // zero-init

__device__ __forceinline__ float sigf(float x) { return 1.0f / (1.0f + expf(-x)); }

// ---------------- grid barrier (monotonic counter, wrap-safe) ----------------
__device__ __forceinline__ void gridbar()
{
    __syncthreads();
    if (threadIdx.x == 0) {
        asm volatile("fence.acq_rel.gpu;" ::: "memory");
        unsigned old = atomicAdd(&g_barcnt, 1u);
        unsigned target = old - (old % (unsigned)NBLK) + (unsigned)NBLK;
        unsigned cur;
        do {
            asm volatile("ld.acquire.gpu.u32 %0, [%1];" : "=r"(cur) : "l"(&g_barcnt));
        } while ((int)(cur - target) < 0);
    }
    __syncthreads();
}

// ---------------- setup kernels (unchanged from round 2) ----------------
__global__ void k_sort(const int* __restrict__ lens, const int* __restrict__ caps,
                       float* __restrict__ out)
{
    int i = threadIdx.x;
    int li = lens[i];
    int r = 0;
    for (int j = 0; j < Bq; j++) {
        int lj = lens[j];
        if (lj > li || (lj == li && j < i)) r++;
    }
    g_sortind[r] = i;
    __syncthreads();
    int src = g_sortind[i];
    int dl = lens[src] - 1;
    g_declen[i] = dl;
    out[OUT_DECLEN + i]  = (float)dl;
    out[OUT_SORTIND + i] = (float)src;
    for (int tt = 0; tt < Tq; tt++) {
        int v = caps[src * Tq + tt];
        g_caps[i * Tq + tt] = v;
        out[OUT_CAPS + i * Tq + tt] = (float)v;
    }
}

__global__ void k_gather(const float* __restrict__ eo)
{
    int bp = blockIdx.x;
    int b = bp / Pq, p = bp % Pq;
    int src = g_sortind[b];
    const float4* s = (const float4*)(eo + ((long long)(src * Pq + p)) * EDq);
    float4* d = (float4*)(g_eos + (long long)bp * EDq);
    for (int i = threadIdx.x; i < EDq / 4; i += blockDim.x) d[i] = s[i];
}

__global__ void k_wcat(const float* __restrict__ Wih, const float* __restrict__ Whh,
                       const float* __restrict__ bih, const float* __restrict__ bhh,
                       const float* __restrict__ Wda, const float* __restrict__ Wfb)
{
    long long idx = (long long)blockIdx.x * blockDim.x + threadIdx.x;
    long long n1 = (long long)KCAT * G4;
    if (idx < n1) {
        int row = (int)(idx / G4), col = (int)(idx % G4);
        g_wcat[idx] = (row < 2348) ? Wih[idx] : Whh[(long long)(row - 2348) * G4 + col];
    }
    long long idx2 = idx - n1;
    if (idx2 >= 0 && idx2 < (long long)DDq * HP) {
        int row = (int)(idx2 / HP), col = (int)(idx2 % HP);
        g_whcat[idx2] = (col < ADq) ? Wda[(long long)row * ADq + col]
                                    : Wfb[(long long)row * EDq + (col - ADq)];
    }
    if (idx < G4) g_biasg[idx] = bih[idx] + bhh[idx];
}

__global__ void k_mean()
{
    int b = blockIdx.y;
    int e = blockIdx.x * 256 + threadIdx.x;
    float s = 0.0f;
    const float* base = g_eos + (long long)b * Pq * EDq + e;
    for (int p = 0; p < Pq; p++) s += base[(long long)p * EDq];
    g_meaneo[b * EDq + e] = s * (1.0f / (float)Pq);
}

// round-2 setup GEMM (64xMtiles x 128 tile, 8x8 micro, 128 threads)
__global__ void __launch_bounds__(128)
k_gemm2(const float* __restrict__ A, int lda,
        const float* __restrict__ B, int ldb,
        float* __restrict__ C, int ldcRow, long long cSplitStride,
        int N, int K, int S,
        const float* __restrict__ bias, int mode)
{
    int nt = blockIdx.x, mt = blockIdx.y, z = blockIdx.z;
    int kchunk = ((K + 16 * S - 1) / (16 * S)) * 16;
    int k0 = z * kchunk;
    int k1 = min(K, k0 + kchunk);
    C += (long long)z * cSplitStride;
    int col0 = nt * 128;
    int row0 = mt * 64;

    __shared__ float As[16][64];
    __shared__ float Bs[16][128];
    int tid = threadIdx.x;
    int tx = tid & 15, ty = tid >> 4;
    float acc[8][8] = {};

    for (int kb = k0; kb < k1; kb += 16) {
#pragma unroll
        for (int l = 0; l < 2; l++) {
            int idx = tid + l * 128;
            int m = idx >> 2;
            int kq = (idx & 3) * 4;
            int kg = kb + kq;
            float4 v = make_float4(0.f, 0.f, 0.f, 0.f);
            if (kg + 3 < k1) {
                v = *(const float4*)&A[(long long)(row0 + m) * lda + kg];
            } else {
                float tmp[4] = {0.f, 0.f, 0.f, 0.f};
                for (int j = 0; j < 4; j++) if (kg + j < k1) tmp[j] = A[(long long)(row0 + m) * lda + kg + j];
                v = make_float4(tmp[0], tmp[1], tmp[2], tmp[3]);
            }
            As[kq + 0][m] = v.x; As[kq + 1][m] = v.y; As[kq + 2][m] = v.z; As[kq + 3][m] = v.w;
        }
#pragma unroll
        for (int l = 0; l < 4; l++) {
            int idx = tid + l * 128;
            int kk = idx >> 5;
            int n4 = (idx & 31) * 4;
            int kg = kb + kk, ng = col0 + n4;
            float4 v = make_float4(0.f, 0.f, 0.f, 0.f);
            if (kg < k1) {
                if (ng + 3 < N) {
                    v = *(const float4*)&B[(long long)kg * ldb + ng];
                } else {
                    float tmp[4] = {0.f, 0.f, 0.f, 0.f};
                    for (int j = 0; j < 4; j++) if (ng + j < N) tmp[j] = B[(long long)kg * ldb + ng + j];
                    v = make_float4(tmp[0], tmp[1], tmp[2], tmp[3]);
                }
            }
            *(float4*)&Bs[kk][n4] = v;
        }
        __syncthreads();
#pragma unroll
        for (int kk = 0; kk < 16; kk++) {
            float a[8], bb[8];
            *(float4*)&a[0] = *(const float4*)&As[kk][ty * 8];
            *(float4*)&a[4] = *(const float4*)&As[kk][ty * 8 + 4];
            *(float4*)&bb[0] = *(const float4*)&Bs[kk][tx * 8];
            *(float4*)&bb[4] = *(const float4*)&Bs[kk][tx * 8 + 4];
#pragma unroll
            for (int i = 0; i < 8; i++)
#pragma unroll
                for (int j = 0; j < 8; j++) acc[i][j] += a[i] * bb[j];
        }
        __syncthreads();
    }

#pragma unroll
    for (int i = 0; i < 8; i++) {
        int m = row0 + ty * 8 + i;
#pragma unroll
        for (int j = 0; j < 8; j++) {
            int n = col0 + tx * 8 + j;
            if (n < N) {
                float v = acc[i][j];
                if (mode == 0) v += bias[n];
                C[(long long)m * ldcRow + n] = v;
            }
        }
    }
}

__global__ void k_reduce(float* __restrict__ dst, int lddst,
                         const float* __restrict__ bias,
                         int N, int S)
{
    int idx = blockIdx.x * 256 + threadIdx.x;
    if (idx >= Bq * N) return;
    int n = idx % N;
    float v = 0.0f;
    for (int s = 0; s < S; s++) v += g_part[(long long)s * Bq * N + idx];
    v += bias[n];
    dst[idx] = v;
}

// ================= persistent loop kernel =================

// 64x128 tile GEMM partial, 256 threads, 8x4 micro, register double-buffer.
__device__ __forceinline__ void gemm64x128(const float* __restrict__ A, int lda,
    const float* __restrict__ B, int ldb, float* __restrict__ C, int ldc,
    int col0, int N, int k0, int k1, float* SH)
{
    float* As = SH;          // [16][64]
    float* Bs = SH + 1024;   // [16][128]
    int tid = threadIdx.x;
    int tx = tid & 31, ty = tid >> 5;
    float acc[8][4] = {};

    int am  = tid & 63;
    int akq = (tid >> 6) << 2;          // 0,4,8,12
    int bkk0 = tid >> 5;                // 0..7
    int bkk1 = bkk0 + 8;                // 8..15
    int bn   = (tid & 31) << 2;

    float4 pa, pb0, pb1;

    // ---- initial fetch (kb = k0) ----
    {
        int kg = k0 + akq;
        if (kg + 3 < k1) pa = *(const float4*)&A[(long long)am * lda + kg];
        else {
            float t0 = (kg     < k1) ? A[(long long)am * lda + kg    ] : 0.f;
            float t1 = (kg + 1 < k1) ? A[(long long)am * lda + kg + 1] : 0.f;
            float t2 = (kg + 2 < k1) ? A[(long long)am * lda + kg + 2] : 0.f;
            float t3 = (kg + 3 < k1) ? A[(long long)am * lda + kg + 3] : 0.f;
            pa = make_float4(t0, t1, t2, t3);
        }
        int kgb0 = k0 + bkk0, kgb1 = k0 + bkk1, ng = col0 + bn;
        pb0 = make_float4(0.f,0.f,0.f,0.f); pb1 = make_float4(0.f,0.f,0.f,0.f);
        if (kgb0 < k1) {
            if (ng + 3 < N) pb0 = *(const float4*)&B[(long long)kgb0 * ldb + ng];
            else for (int j = 0; j < 4; j++) if (ng + j < N) ((float*)&pb0)[j] = B[(long long)kgb0 * ldb + ng + j];
        }
        if (kgb1 < k1) {
            if (ng + 3 < N) pb1 = *(const float4*)&B[(long long)kgb1 * ldb + ng];
            else for (int j = 0; j < 4; j++) if (ng + j < N) ((float*)&pb1)[j] = B[(long long)kgb1 * ldb + ng + j];
        }
    }

    for (int kb = k0; kb < k1; kb += 16) {
        As[(akq + 0) * 64 + am] = pa.x;
        As[(akq + 1) * 64 + am] = pa.y;
        As[(akq + 2) * 64 + am] = pa.z;
        As[(akq + 3) * 64 + am] = pa.w;
        *(float4*)&Bs[bkk0 * 128 + bn] = pb0;
        *(float4*)&Bs[bkk1 * 128 + bn] = pb1;
        __syncthreads();

        int kn = kb + 16;
        if (kn < k1) {
            int kg = kn + akq;
            if (kg + 3 < k1) pa = *(const float4*)&A[(long long)am * lda + kg];
            else {
                float t0 = (kg     < k1) ? A[(long long)am * lda + kg    ] : 0.f;
                float t1 = (kg + 1 < k1) ? A[(long long)am * lda + kg + 1] : 0.f;
                float t2 = (kg + 2 < k1) ? A[(long long)am * lda + kg + 2] : 0.f;
                float t3 = (kg + 3 < k1) ? A[(long long)am * lda + kg + 3] : 0.f;
                pa = make_float4(t0, t1, t2, t3);
            }
            int kgb0 = kn + bkk0, kgb1 = kn + bkk1, ng = col0 + bn;
            pb0 = make_float4(0.f,0.f,0.f,0.f); pb1 = make_float4(0.f,0.f,0.f,0.f);
            if (kgb0 < k1) {
                if (ng + 3 < N) pb0 = *(const float4*)&B[(long long)kgb0 * ldb + ng];
                else for (int j = 0; j < 4; j++) if (ng + j < N) ((float*)&pb0)[j] = B[(long long)kgb0 * ldb + ng + j];
            }
            if (kgb1 < k1) {
                if (ng + 3 < N) pb1 = *(const float4*)&B[(long long)kgb1 * ldb + ng];
                else for (int j = 0; j < 4; j++) if (ng + j < N) ((float*)&pb1)[j] = B[(long long)kgb1 * ldb + ng + j];
            }
        }

#pragma unroll
        for (int kk = 0; kk < 16; kk++) {
            float a0[4], a1[4], bb[4];
            *(float4*)&a0[0] = *(const float4*)&As[kk * 64 + ty * 8];
            *(float4*)&a1[0] = *(const float4*)&As[kk * 64 + ty * 8 + 4];
            *(float4*)&bb[0] = *(const float4*)&Bs[kk * 128 + tx * 4];
#pragma unroll
            for (int i = 0; i < 4; i++)
#pragma unroll
                for (int j = 0; j < 4; j++) {
                    acc[i][j]     += a0[i] * bb[j];
                    acc[i + 4][j] += a1[i] * bb[j];
                }
        }
        __syncthreads();
    }

#pragma unroll
    for (int i = 0; i < 8; i++) {
        int m = ty * 8 + ((i < 4) ? i : (i - 4) + 4);  // = ty*8 + i
#pragma unroll
        for (int j = 0; j < 4; j++) {
            int n = col0 + tx * 4 + j;
            if (n < N) C[(long long)m * ldc + n] = acc[i][j];
        }
    }
}

__device__ void attention_block(int b, int t, const float* __restrict__ wfull,
                                const float* __restrict__ bfull,
                                const float* __restrict__ bda,
                                float* __restrict__ out, float* SH)
{
    float* sh_att2 = SH;          // 512
    float* sh_w    = SH + 512;    // 512
    float* sh_e    = SH + 1024;   // 224
    float* red     = SH + 1248;   // 8
    int tid = threadIdx.x;

    for (int i = tid; i < ADq; i += 256) {
        float v = g_partH[0LL * Bq * HP + b * HP + i]
                + g_partH[1LL * Bq * HP + b * HP + i]
                + g_partH[2LL * Bq * HP + b * HP + i]
                + g_partH[3LL * Bq * HP + b * HP + i] + bda[i];
        sh_att2[i] = v;
        sh_w[i] = wfull[i];
    }
    __syncthreads();

    int wrp = tid >> 5, lane = tid & 31;
    const float4* A1 = (const float4*)(g_att1 + (long long)b * Pq * ADq);
    const float4* T4 = (const float4*)sh_att2;
    const float4* W4 = (const float4*)sh_w;
    for (int p = wrp; p < Pq; p += 8) {
        float s = 0.0f;
#pragma unroll
        for (int j = 0; j < 4; j++) {
            int idx = j * 32 + lane;
            float4 a = A1[p * 128 + idx];
            float4 tt = T4[idx];
            float4 w = W4[idx];
            float v0 = fmaxf(a.x + tt.x, 0.f);
            float v1 = fmaxf(a.y + tt.y, 0.f);
            float v2 = fmaxf(a.z + tt.z, 0.f);
            float v3 = fmaxf(a.w + tt.w, 0.f);
            s += v0 * w.x + v1 * w.y + v2 * w.z + v3 * w.w;
        }
        for (int o = 16; o > 0; o >>= 1) s += __shfl_down_sync(0xffffffffu, s, o);
        if (lane == 0) sh_e[p] = s + bfull[0];
    }
    __syncthreads();

    float mval = -1e30f;
    if (tid < Pq) mval = sh_e[tid];
    for (int o = 16; o > 0; o >>= 1) mval = fmaxf(mval, __shfl_down_sync(0xffffffffu, mval, o));
    if (lane == 0) red[wrp] = mval;
    __syncthreads();
    if (tid == 0) {
        float m2 = red[0];
        for (int i = 1; i < 8; i++) m2 = fmaxf(m2, red[i]);
        red[0] = m2;
    }
    __syncthreads();
    float mx = red[0];
    __syncthreads();

    float ex = 0.0f;
    if (tid < Pq) { ex = expf(sh_e[tid] - mx); sh_e[tid] = ex; }
    float se = ex;
    for (int o = 16; o > 0; o >>= 1) se += __shfl_down_sync(0xffffffffu, se, o);
    if (lane == 0) red[wrp] = se;
    __syncthreads();
    if (tid == 0) {
        float s2 = 0.0f;
        for (int i = 0; i < 8; i++) s2 += red[i];
        red[0] = s2;
    }
    __syncthreads();
    float ssum = red[0];

    float mk = (g_declen[b] > t) ? 1.0f : 0.0f;
    if (tid < Pq) {
        float al = sh_e[tid] / ssum;
        g_alpha[b * Pq + tid] = al;
        out[OUT_ALPHAS + (long long)b * TD * Pq + (long long)t * Pq + tid] = al * mk;
    }
    __syncthreads();
}

__device__ void preds_reduce_block(int b, int tp, const float* __restrict__ bfc,
                                   float* __restrict__ out)
{
    int tid = threadIdx.x;
    float mk = (g_declen[b] > tp) ? 1.0f : 0.0f;
    for (int n = tid; n < Vq; n += 256) {
        float v = bfc[n];
#pragma unroll
        for (int s = 0; s < 8; s++) v += g_partP[(long long)s * Bq * Vq + b * Vq + n];
        out[OUT_PRED + (long long)b * TD * Vq + (long long)tp * Vq + n] = v * mk;
    }
}

__device__ void awe_task(int b, int e0, const float* __restrict__ bfb, float* SH)
{
    float* sa = SH;   // 196
    int tid = threadIdx.x;
    __syncthreads();
    if (tid < Pq) sa[tid] = g_alpha[b * Pq + tid];
    __syncthreads();

    int e = e0 + tid * 4;
    const float4* base = (const float4*)(g_eos + (long long)b * Pq * EDq);
    int c4 = e >> 2;
    float4 acc0 = make_float4(0.f, 0.f, 0.f, 0.f);
    float4 acc1 = make_float4(0.f, 0.f, 0.f, 0.f);
#pragma unroll 4
    for (int p = 0; p < Pq; p += 2) {
        float a0 = sa[p], a1 = sa[p + 1];
        float4 v0 = base[(long long)p * 512 + c4];
        float4 v1 = base[(long long)(p + 1) * 512 + c4];
        acc0.x += a0 * v0.x; acc0.y += a0 * v0.y; acc0.z += a0 * v0.z; acc0.w += a0 * v0.w;
        acc1.x += a1 * v1.x; acc1.y += a1 * v1.y; acc1.z += a1 * v1.z; acc1.w += a1 * v1.w;
    }
    acc0.x += acc1.x; acc0.y += acc1.y; acc0.z += acc1.z; acc0.w += acc1.w;

    float4 gs = make_float4(0.f, 0.f, 0.f, 0.f);
#pragma unroll
    for (int s = 0; s < 4; s++) {
        float4 g = *(const float4*)&g_partH[(long long)s * Bq * HP + b * HP + ADq + e];
        gs.x += g.x; gs.y += g.y; gs.z += g.z; gs.w += g.w;
    }
    float4 bb = *(const float4*)&bfb[e];
    float4 r;
    r.x = sigf(gs.x + bb.x) * acc0.x;
    r.y = sigf(gs.y + bb.y) * acc0.y;
    r.z = sigf(gs.z + bb.z) * acc0.z;
    r.w = sigf(gs.w + bb.w) * acc0.w;
    *(float4*)&g_xcat[b * KCAT + Eq + e] = r;
}

__device__ void cell_block(int b, int t)
{
    int tid = threadIdx.x;
    for (int d = tid; d < DDq; d += 256) {
        float i_ = g_biasg[d], f_ = g_biasg[512 + d];
        float gg = g_biasg[1024 + d], o_ = g_biasg[1536 + d];
#pragma unroll
        for (int s = 0; s < 9; s++) {
            const float* p = g_partG + (long long)s * Bq * G4 + b * G4;
            i_ += p[d]; f_ += p[512 + d]; gg += p[1024 + d]; o_ += p[1536 + d];
        }
        float co = g_c[b * DDq + d], ho = g_h[b * DDq + d];
        float cn = sigf(f_) * co + sigf(i_) * tanhf(gg);
        float hn = sigf(o_) * tanhf(cn);
        bool mk = (g_declen[b] > t);
        g_h[b * DDq + d] = mk ? hn : ho;
        g_c[b * DDq + d] = mk ? cn : co;
    }
}

__global__ void __launch_bounds__(256)
k_loop(const float* __restrict__ emb, const float* __restrict__ wfull,
       const float* __restrict__ bfull, const float* __restrict__ bda,
       const float* __restrict__ bfb, const float* __restrict__ Wfc,
       const float* __restrict__ bfc, float* __restrict__ out)
{
    __shared__ float SH[3072];
    int bid = blockIdx.x;

    for (int t = 0; t <= TD; t++) {
        // ---- phase 1: hproj partials | preds(t-1) partials | xcat staging ----
        if (t < TD && bid < 80) {
            int nt = bid >> 2, s = bid & 3;
            gemm64x128(g_h, DDq, g_whcat, HP, g_partH + (long long)s * Bq * HP, HP,
                       nt * 128, HP, s * 128, s * 128 + 128, SH);
        } else if (t > 0 && bid >= 80 && bid < 144) {
            int q = bid - 80, nt = q >> 3, s = q & 7;
            gemm64x128(g_h, DDq, Wfc, Vq, g_partP + (long long)s * Bq * Vq, Vq,
                       nt * 128, Vq, s * 64, s * 64 + 64, SH);
        } else if (t < TD && bid >= 144) {
            for (int b = (bid - 144) * 16; b < (bid - 143) * 16; b++) {
                int tok = g_caps[b * Tq + t];
                for (int i = threadIdx.x; i < Eq; i += 256)
                    g_xcat[b * KCAT + i] = emb[(long long)tok * Eq + i];
                for (int i = threadIdx.x; i < DDq; i += 256)
                    g_xcat[b * KCAT + 2348 + i] = g_h[b * DDq + i];
            }
        }
        gridbar();

        // ---- phase 2: attention | preds reduce ----
        if (bid < 64) {
            if (t < TD) attention_block(bid, t, wfull, bfull, bda, out, SH);
        } else if (bid < 128 && t > 0) {
            preds_reduce_block(bid - 64, t - 1, bfc, out);
        }
        gridbar();

        if (t == TD) break;

        // ---- phase 3: awe + gate fusion ----
        for (int task = bid; task < 128; task += NBLK)
            awe_task(task >> 1, (task & 1) * 1024, bfb, SH);
        gridbar();

        // ---- phase 4: LSTM gates partials ----
        if (bid < 144) {
            int nt = bid / 9, s = bid % 9;
            int k0 = s * 320;
            int k1 = min(KCAT, k0 + 320);
            gemm64x128(g_xcat, KCAT, g_wcat, G4, g_partG + (long long)s * Bq * G4, G4,
                       nt * 128, G4, k0, k1, SH);
        }
        gridbar();

        // ---- phase 5: cell ----
        if (bid < 64) cell_block(bid, t);
        gridbar();
    }
}

// =================================================================================
extern "C" void kernel_launch(void* const* d_in, const int* in_sizes, int n_in,
                              void* d_out, int out_size)
{
    const float* eo    = (const float*)d_in[0];
    const int*   caps  = (const int*)  d_in[1];
    const int*   lens  = (const int*)  d_in[2];
    const float* emb   = (const float*)d_in[3];
    const float* Wea   = (const float*)d_in[4];
    const float* bea   = (const float*)d_in[5];
    const float* Wda   = (const float*)d_in[6];
    const float* bda   = (const float*)d_in[7];
    const float* wfull = (const float*)d_in[8];
    const float* bfull = (const float*)d_in[9];
    const float* Wih0  = (const float*)d_in[10];
    const float* bih0  = (const float*)d_in[11];
    const float* Wic0  = (const float*)d_in[12];
    const float* bic0  = (const float*)d_in[13];
    const float* Wfb   = (const float*)d_in[14];
    const float* bfb   = (const float*)d_in[15];
    const float* WIH   = (const float*)d_in[16];
    const float* bIH   = (const float*)d_in[17];
    const float* WHH   = (const float*)d_in[18];
    const float* bHH   = (const float*)d_in[19];
    const float* Wfc   = (const float*)d_in[20];
    const float* bfc   = (const float*)d_in[21];
    float* out = (float*)d_out;

    float *p_eos, *p_att1, *p_meaneo, *p_h, *p_c, *p_part;
    cudaGetSymbolAddress((void**)&p_eos, g_eos);
    cudaGetSymbolAddress((void**)&p_att1, g_att1);
    cudaGetSymbolAddress((void**)&p_meaneo, g_meaneo);
    cudaGetSymbolAddress((void**)&p_h, g_h);
    cudaGetSymbolAddress((void**)&p_c, g_c);
    cudaGetSymbolAddress((void**)&p_part, g_part);

    // ---- setup ----
    k_sort<<<1, Bq>>>(lens, caps, out);
    {
        long long tot = (long long)KCAT * G4 + (long long)DDq * HP;
        k_wcat<<<(int)((tot + 1023) / 1024), 1024>>>(WIH, WHH, bIH, bHH, Wda, Wfb);
    }
    k_gather<<<Bq * Pq, 256>>>(eo);
    k_mean<<<dim3(8, Bq), 256>>>();
    // h0 = mean_eo @ W_init_h + b (M=64, K=2048, N=512), split-K 8
    k_gemm2<<<dim3(4, 1, 8), 128>>>(p_meaneo, EDq, Wih0, DDq, p_part, DDq,
                                    (long long)Bq * DDq, DDq, EDq, 8, (const float*)0, 2);
    k_reduce<<<(Bq * DDq + 255) / 256, 256>>>(p_h, DDq, bih0, DDq, 8);
    k_gemm2<<<dim3(4, 1, 8), 128>>>(p_meaneo, EDq, Wic0, DDq, p_part, DDq,
                                    (long long)Bq * DDq, DDq, EDq, 8, (const float*)0, 2);
    k_reduce<<<(Bq * DDq + 255) / 256, 256>>>(p_c, DDq, bic0, DDq, 8);
    // att1 = eo_s @ W_enc_att + b  (M=12544, K=2048, N=512)
    k_gemm2<<<dim3(4, 196, 1), 128>>>(p_eos, EDq, Wea, ADq, p_att1, ADq, 0,
                                      ADq, EDq, 1, bea, 0);

    // ---- persistent recurrence ----
    k_loop<<<NBLK, 256>>>(emb, wfull, bfull, bda, bfb, Wfc, bfc, out);
}